// round 17
// baseline (speedup 1.0000x reference)
#include <cuda_runtime.h>
#include <cuda_bf16.h>
#include <math.h>
#include <stdint.h>

// ---------------- problem constants ----------------
static const int BB    = 8;
static const int NR    = 1024;
static const int NSEQ  = 2048;
static const int FEAT  = 768;
static const int HIDD  = 256;
static const int GATD  = 128;
static const int GRUD  = 64;
static const int MTOT  = BB * NSEQ;   // 16384
static const int CAP   = 512;
static const int GCH   = 64;          // GRU chunk length
static const int GWU   = 128;         // GRU warm-up steps
static const int NCHK  = NSEQ / GCH;  // 32

// ---------------- scratch ----------------
__device__ unsigned short g_abf[(size_t)MTOT * FEAT];
__device__ unsigned short g_wbf[HIDD * FEAT];
__device__ unsigned short g_pbf[(size_t)MTOT * HIDD];
__device__ unsigned short g_wg1b[HIDD * HIDD];
__device__ unsigned short g_wg2b[GATD * HIDD];
__device__ unsigned short g_h1b[(size_t)MTOT * HIDD];
__device__ unsigned short g_g1b[(size_t)MTOT * HIDD];
__device__ unsigned short g_h2b[(size_t)MTOT * GATD];
__device__ unsigned short g_gatb[(size_t)MTOT * GATD];
__device__ unsigned short g_wifb[192 * GATD];
__device__ unsigned short g_wibb[192 * GATD];
__device__ float g_s1s [BB * NSEQ];
__device__ float g_s1d [BB * NSEQ];
__device__ float g_s2s [BB * NSEQ];
__device__ float g_s2d [BB * NSEQ];
__device__ float g_xall[BB * NSEQ * 384];
__device__ float g_pool[BB * 2 * GRUD];
__device__ unsigned short g_el [ (size_t)MTOT * CAP ];
__device__ int            g_deg[ MTOT ];

// ---------------- helpers ----------------
typedef unsigned long long ull;
__device__ __forceinline__ ull pk2(float lo, float hi) {
    ull r; asm("mov.b64 %0, {%1, %2};" : "=l"(r) : "f"(lo), "f"(hi)); return r;
}
__device__ __forceinline__ void upk2(ull v, float& lo, float& hi) {
    asm("mov.b64 {%0, %1}, %2;" : "=f"(lo), "=f"(hi) : "l"(v));
}
__device__ __forceinline__ ull ffma2(ull a, ull b, ull c) {
    ull d; asm("fma.rn.f32x2 %0, %1, %2, %3;" : "=l"(d) : "l"(a), "l"(b), "l"(c)); return d;
}
__device__ __forceinline__ ull fadd2(ull a, ull b) {
    ull d; asm("add.rn.f32x2 %0, %1, %2;" : "=l"(d) : "l"(a), "l"(b)); return d;
}
__device__ __forceinline__ float fast_tanh(float x) {
    float y; asm("tanh.approx.f32 %0, %1;" : "=f"(y) : "f"(x)); return y;
}
__device__ __forceinline__ float fast_sig(float x) {
    return fmaf(0.5f, fast_tanh(0.5f * x), 0.5f);
}
__device__ __forceinline__ void bf2f(unsigned u, float& a, float& b) {
    a = __uint_as_float(u << 16);
    b = __uint_as_float(u & 0xffff0000u);
}
__device__ __forceinline__ unsigned f2bf2(float a, float b) {
    unsigned sa = __bfloat16_as_ushort(__float2bfloat16(a));
    unsigned sb = __bfloat16_as_ushort(__float2bfloat16(b));
    return sa | (sb << 16);
}
__device__ __forceinline__ void mma16816(float* d, const unsigned* a, const unsigned* b) {
    asm volatile(
        "mma.sync.aligned.m16n8k16.row.col.f32.bf16.bf16.f32 "
        "{%0,%1,%2,%3}, {%4,%5,%6,%7}, {%8,%9}, {%0,%1,%2,%3};"
        : "+f"(d[0]), "+f"(d[1]), "+f"(d[2]), "+f"(d[3])
        : "r"(a[0]), "r"(a[1]), "r"(a[2]), "r"(a[3]), "r"(b[0]), "r"(b[1]));
}
__device__ __forceinline__ void ldsm4(unsigned& r0, unsigned& r1, unsigned& r2, unsigned& r3,
                                      unsigned addr) {
    asm volatile("ldmatrix.sync.aligned.m8n8.x4.shared.b16 {%0,%1,%2,%3}, [%4];"
                 : "=r"(r0), "=r"(r1), "=r"(r2), "=r"(r3) : "r"(addr));
}
__device__ __forceinline__ unsigned smem_u32(const void* p) {
    unsigned a;
    asm("{ .reg .u64 t; cvta.to.shared.u64 t, %1; cvt.u32.u64 %0, t; }" : "=r"(a) : "l"(p));
    return a;
}

// ---------------- CSR edge-list build (float4 loads) + s-array + pool zeroing ------------
__global__ __launch_bounds__(256)
void build_csr_kernel(const float* __restrict__ adj, unsigned short* __restrict__ el,
                      int* __restrict__ deg,
                      float* __restrict__ s1s, float* __restrict__ s1d,
                      float* __restrict__ s2s, float* __restrict__ s2d,
                      float* __restrict__ pool) {
    if (threadIdx.x < 8) {
        int r = blockIdx.x * 8 + threadIdx.x;
        s1s[r] = 0.f; s1d[r] = 0.f; s2s[r] = 0.f; s2d[r] = 0.f;
    }
    if (blockIdx.x == 0) {
        for (int q = threadIdx.x; q < BB * 2 * GRUD; q += 256) pool[q] = 0.f;
    }
    int lane = threadIdx.x & 31;
    int warp = threadIdx.x >> 5;
    int row = blockIdx.x * 8 + warp;
    const float* ar = adj + (size_t)row * NSEQ;
    unsigned short* er = el + (size_t)row * CAP;
    int cnt = 0;
    unsigned below = (1u << lane) - 1u;
    for (int j0 = 0; j0 < NSEQ; j0 += 128) {
        float4 v = *(const float4*)(ar + j0 + lane * 4);
        unsigned m0 = __ballot_sync(0xffffffffu, v.x > 0.f);
        unsigned m1 = __ballot_sync(0xffffffffu, v.y > 0.f);
        unsigned m2 = __ballot_sync(0xffffffffu, v.z > 0.f);
        unsigned m3 = __ballot_sync(0xffffffffu, v.w > 0.f);
        int base = cnt + __popc(m0 & below) + __popc(m1 & below)
                       + __popc(m2 & below) + __popc(m3 & below);
        int off = 0;
        int col = j0 + 4 * lane;
        if (v.x > 0.f) { int p = base + off; if (p < CAP) er[p] = (unsigned short)(col + 0); off++; }
        if (v.y > 0.f) { int p = base + off; if (p < CAP) er[p] = (unsigned short)(col + 1); off++; }
        if (v.z > 0.f) { int p = base + off; if (p < CAP) er[p] = (unsigned short)(col + 2); off++; }
        if (v.w > 0.f) { int p = base + off; if (p < CAP) er[p] = (unsigned short)(col + 3); off++; }
        cnt += __popc(m0) + __popc(m1) + __popc(m2) + __popc(m3);
    }
    if (lane == 0) deg[row] = cnt < CAP ? cnt : CAP;
}

// ---------------- bf16 conversions ----------------
__global__ __launch_bounds__(256)
void conv_a_kernel(const float4* __restrict__ req, const float4* __restrict__ code,
                   ull* __restrict__ abf) {
    size_t idx = (size_t)blockIdx.x * 256 + threadIdx.x;
    const int G = FEAT / 4;
    if (idx >= (size_t)MTOT * G) return;
    int m = (int)(idx / G);
    int g = (int)(idx % G);
    int b = m >> 11, i = m & 2047;
    float4 v = (i < NR) ? req[((size_t)b * NR + i) * G + g]
                        : code[((size_t)b * NR + (i - NR)) * G + g];
    union { unsigned short s[4]; ull u; } pk;
    pk.s[0] = __bfloat16_as_ushort(__float2bfloat16(v.x));
    pk.s[1] = __bfloat16_as_ushort(__float2bfloat16(v.y));
    pk.s[2] = __bfloat16_as_ushort(__float2bfloat16(v.z));
    pk.s[3] = __bfloat16_as_ushort(__float2bfloat16(v.w));
    abf[idx] = pk.u;
}

__global__ __launch_bounds__(256)
void conv_w_kernel(const float4* __restrict__ W, ull* __restrict__ wbf, int n4) {
    int idx = blockIdx.x * 256 + threadIdx.x;
    if (idx >= n4) return;
    float4 v = W[idx];
    union { unsigned short s[4]; ull u; } pk;
    pk.s[0] = __bfloat16_as_ushort(__float2bfloat16(v.x));
    pk.s[1] = __bfloat16_as_ushort(__float2bfloat16(v.y));
    pk.s[2] = __bfloat16_as_ushort(__float2bfloat16(v.z));
    pk.s[3] = __bfloat16_as_ushort(__float2bfloat16(v.w));
    wbf[idx] = pk.u;
}

// ---------------- unified HMMA GEMM: smem-staged + ldmatrix ----------------
template <int KD, int DOUT, int EPI>
__global__ __launch_bounds__(256)
void hmma_smem_kernel(const unsigned short* __restrict__ Ag,
                      const unsigned short* __restrict__ Wg,
                      const float* __restrict__ bias, const float* __restrict__ avec,
                      unsigned short* __restrict__ Hout,
                      float* __restrict__ ssrc, float* __restrict__ sdst,
                      float* __restrict__ Fout, int ostr) {
    const int NF   = DOUT / 32;
    const int BROW = DOUT / 64;
    const int NS   = KD / 32;
    __shared__ unsigned short sA[2][64 * 32];
    __shared__ unsigned short sB[2][DOUT * 32];

    int tid = threadIdx.x;
    int warp = tid >> 5, lane = tid & 31;
    int g = lane >> 2, tg = lane & 3;
    int wm = warp & 1, wn = warp >> 1;
    int mblk = blockIdx.x * 64;
    int n0w = wn * (DOUT / 4);

    int arow = tid >> 2, achk = tid & 3;
    const unsigned short* abase = Ag + (size_t)(mblk + arow) * KD + achk * 8;
    int asw = arow * 32 + ((achk ^ (arow & 3)) * 8);
    int bsw[BROW];
    const unsigned short* bbase[BROW];
#pragma unroll
    for (int i = 0; i < BROW; i++) {
        int brow = arow + 64 * i;
        bbase[i] = Wg + (size_t)brow * KD + achk * 8;
        bsw[i] = brow * 32 + ((achk ^ (brow & 3)) * 8);
    }

    unsigned baseA = smem_u32(&sA[0][0]);
    unsigned baseB = smem_u32(&sB[0][0]);
    const unsigned bufBytesA = 64 * 32 * 2;
    const unsigned bufBytesB = DOUT * 32 * 2;

    int lmat = lane >> 3, lr = lane & 7;
    int rowAl[2], halfA = lane >> 4;
#pragma unroll
    for (int mf = 0; mf < 2; mf++)
        rowAl[mf] = wm * 32 + mf * 16 + (lmat & 1) * 8 + lr;
    int halfB = lmat & 1;
    int rowBbase = n0w + ((lane >> 4) * 8) + lr;

    float acc[2][NF][4];
#pragma unroll
    for (int mf = 0; mf < 2; mf++)
#pragma unroll
        for (int nf = 0; nf < NF; nf++)
#pragma unroll
            for (int q = 0; q < 4; q++) acc[mf][nf][q] = 0.f;

    {
        uint4 ra = *(const uint4*)abase;
        *(uint4*)&sA[0][asw] = ra;
#pragma unroll
        for (int i = 0; i < BROW; i++) {
            uint4 rb = *(const uint4*)bbase[i];
            *(uint4*)&sB[0][bsw[i]] = rb;
        }
    }
    __syncthreads();

    for (int s = 0; s < NS; s++) {
        int buf = s & 1;
        uint4 na;
        uint4 nb[BROW];
        bool more = (s + 1 < NS);
        if (more) {
            na = *(const uint4*)(abase + (s + 1) * 32);
#pragma unroll
            for (int i = 0; i < BROW; i++)
                nb[i] = *(const uint4*)(bbase[i] + (s + 1) * 32);
        }
        unsigned bA = baseA + buf * bufBytesA;
        unsigned bB = baseB + buf * bufBytesB;
#pragma unroll
        for (int kk = 0; kk < 2; kk++) {
            unsigned aa[2][4];
#pragma unroll
            for (int mf = 0; mf < 2; mf++) {
                int row = rowAl[mf];
                int chunk = kk * 2 + halfA;
                unsigned addr = bA + (row * 32 + ((chunk ^ (row & 3)) * 8)) * 2;
                ldsm4(aa[mf][0], aa[mf][1], aa[mf][2], aa[mf][3], addr);
            }
            unsigned bb[NF][2];
#pragma unroll
            for (int fp = 0; fp < NF / 2; fp++) {
                int row = rowBbase + fp * 16;
                int chunk = kk * 2 + halfB;
                unsigned addr = bB + (row * 32 + ((chunk ^ (row & 3)) * 8)) * 2;
                ldsm4(bb[2 * fp][0], bb[2 * fp][1], bb[2 * fp + 1][0], bb[2 * fp + 1][1], addr);
            }
#pragma unroll
            for (int mf = 0; mf < 2; mf++)
#pragma unroll
                for (int nf = 0; nf < NF; nf++)
                    mma16816(acc[mf][nf], aa[mf], bb[nf]);
        }
        if (more) {
            int q = buf ^ 1;
            *(uint4*)&sA[q][asw] = na;
#pragma unroll
            for (int i = 0; i < BROW; i++)
                *(uint4*)&sB[q][bsw[i]] = nb[i];
        }
        __syncthreads();
    }

    if (EPI == 0) {
#pragma unroll
        for (int mf = 0; mf < 2; mf++) {
            int r0 = mblk + wm * 32 + mf * 16 + g;
#pragma unroll
            for (int nf = 0; nf < NF; nf++) {
                int col = n0w + nf * 8 + 2 * tg;
                float b0 = bias[col], b1 = bias[col + 1];
                float v0 = fmaxf(acc[mf][nf][0] + b0, 0.f);
                float v1 = fmaxf(acc[mf][nf][1] + b1, 0.f);
                float v2 = fmaxf(acc[mf][nf][2] + b0, 0.f);
                float v3 = fmaxf(acc[mf][nf][3] + b1, 0.f);
                *(unsigned*)&Hout[(size_t)r0 * DOUT + col] = f2bf2(v0, v1);
                *(unsigned*)&Hout[(size_t)(r0 + 8) * DOUT + col] = f2bf2(v2, v3);
            }
        }
    } else if (EPI == 1) {
#pragma unroll
        for (int mf = 0; mf < 2; mf++) {
            int rA = mblk + wm * 32 + mf * 16 + g;
            int rB = rA + 8;
            float psA = 0.f, pdA = 0.f, psB = 0.f, pdB = 0.f;
#pragma unroll
            for (int nf = 0; nf < NF; nf++) {
                int col = n0w + nf * 8 + 2 * tg;
                float b0 = bias[col], b1 = bias[col + 1];
                float as0 = avec[col], as1 = avec[col + 1];
                float ad0 = avec[DOUT + col], ad1 = avec[DOUT + col + 1];
                float v0 = acc[mf][nf][0] + b0;
                float v1 = acc[mf][nf][1] + b1;
                float v2 = acc[mf][nf][2] + b0;
                float v3 = acc[mf][nf][3] + b1;
                *(unsigned*)&Hout[(size_t)rA * DOUT + col] = f2bf2(v0, v1);
                *(unsigned*)&Hout[(size_t)rB * DOUT + col] = f2bf2(v2, v3);
                psA = fmaf(v0, as0, fmaf(v1, as1, psA));
                pdA = fmaf(v0, ad0, fmaf(v1, ad1, pdA));
                psB = fmaf(v2, as0, fmaf(v3, as1, psB));
                pdB = fmaf(v2, ad0, fmaf(v3, ad1, pdB));
            }
#pragma unroll
            for (int off = 1; off < 4; off <<= 1) {
                psA += __shfl_xor_sync(0xffffffffu, psA, off);
                pdA += __shfl_xor_sync(0xffffffffu, pdA, off);
                psB += __shfl_xor_sync(0xffffffffu, psB, off);
                pdB += __shfl_xor_sync(0xffffffffu, pdB, off);
            }
            if (tg == 0) {
                atomicAdd(&ssrc[rA], psA);
                atomicAdd(&sdst[rA], pdA);
                atomicAdd(&ssrc[rB], psB);
                atomicAdd(&sdst[rB], pdB);
            }
        }
    } else {
#pragma unroll
        for (int mf = 0; mf < 2; mf++) {
            int r0 = mblk + wm * 32 + mf * 16 + g;
#pragma unroll
            for (int nf = 0; nf < NF; nf++) {
                int col = n0w + nf * 8 + 2 * tg;
                float b0 = bias[col], b1 = bias[col + 1];
                float2 o0, o1;
                o0.x = acc[mf][nf][0] + b0; o0.y = acc[mf][nf][1] + b1;
                o1.x = acc[mf][nf][2] + b0; o1.y = acc[mf][nf][3] + b1;
                *(float2*)&Fout[(size_t)r0 * ostr + col] = o0;
                *(float2*)&Fout[(size_t)(r0 + 8) * ostr + col] = o1;
            }
        }
    }
}

// ---------------- GAT attention: edge lists, 2-pass softmax, warp/row, bf16 gather ------
template <int D, int ACT, int OUTB>
__global__ __launch_bounds__(256)
void gat_attb_kernel(const unsigned short* __restrict__ hb16,
                     const unsigned short* __restrict__ el,
                     const int* __restrict__ deg, const float* __restrict__ ssrc,
                     const float* __restrict__ sdst, const int* __restrict__ total,
                     float* __restrict__ outf, unsigned short* __restrict__ outb) {
    const int PL = D / 32;
    int lane = threadIdx.x & 31;
    int warp = threadIdx.x >> 5;
    int b = blockIdx.y;
    int i = blockIdx.x * 8 + warp;
    int row = b * NSEQ + i;
    int dg = deg[row];
    const unsigned short* E = el + (size_t)row * CAP;
    const unsigned short* hb = hb16 + (size_t)b * NSEQ * D;
    float si = ssrc[row];
    const float* sd = sdst + b * NSEQ;

    float acc[PL];
#pragma unroll
    for (int q = 0; q < PL; q++) acc[q] = 0.f;
    float inv;

    if (dg > 0) {
        float m = -1e30f;
        for (int e = lane; e < dg; e += 32) {
            int j = E[e];
            float xv = si + sd[j];
            float ev = xv > 0.f ? xv : 0.01f * xv;
            m = fmaxf(m, ev);
        }
#pragma unroll
        for (int off = 16; off > 0; off >>= 1)
            m = fmaxf(m, __shfl_xor_sync(0xffffffffu, m, off));

        float ssum = 0.f;
        for (int e0 = 0; e0 < dg; e0 += 32) {
            int e = e0 + lane;
            int j = 0;
            float p = 0.f;
            if (e < dg) {
                j = E[e];
                float xv = si + sd[j];
                float ev = xv > 0.f ? xv : 0.01f * xv;
                p = __expf(ev - m);
            }
            ssum += p;
            int cnt = dg - e0;
            if (cnt > 32) cnt = 32;
            int cnt8 = (cnt + 7) & ~7;
            for (int t0 = 0; t0 < cnt8; t0 += 8) {
                float pt[8];
                int   jt[8];
#pragma unroll
                for (int u = 0; u < 8; u++) {
                    pt[u] = __shfl_sync(0xffffffffu, p, t0 + u);
                    jt[u] = __shfl_sync(0xffffffffu, j, t0 + u);
                }
                if (PL == 8) {
                    uint4 V[8];
#pragma unroll
                    for (int u = 0; u < 8; u++)
                        V[u] = *(const uint4*)(hb + (size_t)jt[u] * D + lane * 8);
#pragma unroll
                    for (int u = 0; u < 8; u++) {
                        float f0, f1, f2, f3, f4, f5, f6, f7;
                        bf2f(V[u].x, f0, f1); bf2f(V[u].y, f2, f3);
                        bf2f(V[u].z, f4, f5); bf2f(V[u].w, f6, f7);
                        acc[0] = fmaf(pt[u], f0, acc[0]);
                        acc[1] = fmaf(pt[u], f1, acc[1]);
                        acc[2] = fmaf(pt[u], f2, acc[2]);
                        acc[3] = fmaf(pt[u], f3, acc[3]);
                        acc[4] = fmaf(pt[u], f4, acc[4]);
                        acc[5] = fmaf(pt[u], f5, acc[5]);
                        acc[6] = fmaf(pt[u], f6, acc[6]);
                        acc[7] = fmaf(pt[u], f7, acc[7]);
                    }
                } else {
                    uint2 V[8];
#pragma unroll
                    for (int u = 0; u < 8; u++)
                        V[u] = *(const uint2*)(hb + (size_t)jt[u] * D + lane * 4);
#pragma unroll
                    for (int u = 0; u < 8; u++) {
                        float f0, f1, f2, f3;
                        bf2f(V[u].x, f0, f1); bf2f(V[u].y, f2, f3);
                        acc[0] = fmaf(pt[u], f0, acc[0]);
                        acc[1] = fmaf(pt[u], f1, acc[1]);
                        acc[2] = fmaf(pt[u], f2, acc[2]);
                        acc[3] = fmaf(pt[u], f3, acc[3]);
                    }
                }
            }
        }
#pragma unroll
        for (int off = 16; off > 0; off >>= 1)
            ssum += __shfl_xor_sync(0xffffffffu, ssum, off);
        inv = 1.f / ssum;
    } else {
#pragma unroll 1
        for (int j = 0; j < NSEQ; j++) {
            if (PL == 8) {
                uint4 V = *(const uint4*)(hb + (size_t)j * D + lane * 8);
                float f0, f1, f2, f3, f4, f5, f6, f7;
                bf2f(V.x, f0, f1); bf2f(V.y, f2, f3);
                bf2f(V.z, f4, f5); bf2f(V.w, f6, f7);
                acc[0] += f0; acc[1] += f1; acc[2] += f2; acc[3] += f3;
                acc[4] += f4; acc[5] += f5; acc[6] += f6; acc[7] += f7;
            } else {
                uint2 V = *(const uint2*)(hb + (size_t)j * D + lane * 4);
                float f0, f1, f2, f3;
                bf2f(V.x, f0, f1); bf2f(V.y, f2, f3);
                acc[0] += f0; acc[1] += f1; acc[2] += f2; acc[3] += f3;
            }
        }
        inv = 1.f / (float)NSEQ;
    }

    bool on = (i < total[b]);
    float v[PL];
#pragma unroll
    for (int q = 0; q < PL; q++) {
        float x = on ? acc[q] * inv : 0.f;
        if (ACT == 1) x = fmaxf(x, 0.f);
        v[q] = x;
    }
    if (OUTB) {
        unsigned short* op = outb + (size_t)row * D + lane * PL;
#pragma unroll
        for (int q2 = 0; q2 < PL / 2; q2++)
            *(unsigned*)(op + q2 * 2) = f2bf2(v[q2 * 2], v[q2 * 2 + 1]);
    } else {
        float* op = outf + (size_t)row * D + lane * PL;
#pragma unroll
        for (int q4 = 0; q4 < PL / 4; q4++)
            *(float4*)(op + q4 * 4) = make_float4(v[q4 * 4], v[q4 * 4 + 1],
                                                  v[q4 * 4 + 2], v[q4 * 4 + 3]);
    }
}

// ---------------- GRU v4: chunked-parallel with warm-up, fused masked pool ---------------
__global__ __launch_bounds__(128)
void gru_kernel(const float* __restrict__ xall,
                const float* __restrict__ Whh_f, const float* __restrict__ bhh_f,
                const float* __restrict__ Whh_b, const float* __restrict__ bhh_b,
                const int* __restrict__ total, float* __restrict__ pool) {
    int b = blockIdx.x;
    int dir = blockIdx.y;
    int ch = blockIdx.z;
    const float* Whh = dir ? Whh_b : Whh_f;
    const float* bhh = dir ? bhh_b : bhh_f;
    int tid = threadIdx.x;
    int j = tid >> 1;
    int p = tid & 1;
    int tot = total[b];

    int s_real0 = ch * GCH;
    int s_start = s_real0 - GWU; if (s_start < 0) s_start = 0;
    int s_end = s_real0 + GCH;

    __shared__ __align__(16) float hbuf[2][GRUD];

    ull wr_[16], wz_[16], wn_[16];
    {
        const float2* Wr = (const float2*)(Whh + (size_t)j * GRUD + 32 * p);
        const float2* Wz = (const float2*)(Whh + (size_t)(GRUD + j) * GRUD + 32 * p);
        const float2* Wn = (const float2*)(Whh + (size_t)(2 * GRUD + j) * GRUD + 32 * p);
#pragma unroll
        for (int q = 0; q < 16; q++) { float2 v = Wr[q]; wr_[q] = pk2(v.x, v.y); }
#pragma unroll
        for (int q = 0; q < 16; q++) { float2 v = Wz[q]; wz_[q] = pk2(v.x, v.y); }
#pragma unroll
        for (int q = 0; q < 16; q++) { float2 v = Wn[q]; wn_[q] = pk2(v.x, v.y); }
    }
    float br = bhh[j], bz = bhh[GRUD + j], bn = bhh[2 * GRUD + j];

    if (p == 0) hbuf[s_start & 1][j] = 0.f;
    float hprev = 0.f;

    const float* Xb = xall + (size_t)b * NSEQ * 384 + dir * 192;
    float psum = 0.f;

    int t0 = dir ? (NSEQ - 1 - s_start) : s_start;
    float xr = 0.f, xz = 0.f, xn = 0.f;
    if (p == 0) {
        const float* xp = Xb + (size_t)t0 * 384;
        xr = xp[j]; xz = xp[GRUD + j]; xn = xp[2 * GRUD + j];
    }

    for (int s = s_start; s < s_end; s++) {
        int t = dir ? (NSEQ - 1 - s) : s;
        float xrn = 0.f, xzn = 0.f, xnn = 0.f;
        if (p == 0 && s + 1 < s_end) {
            int sn = s + 1;
            int tn = dir ? (NSEQ - 1 - sn) : sn;
            const float* xp = Xb + (size_t)tn * 384;
            xrn = xp[j]; xzn = xp[GRUD + j]; xnn = xp[2 * GRUD + j];
        }
        __syncthreads();
        const ulonglong2* hp2 = (const ulonglong2*)&hbuf[s & 1][32 * p];
        ull r0 = 0, r1 = 0, r2 = 0, r3 = 0;
        ull z0 = 0, z1 = 0, z2 = 0, z3 = 0;
        ull n0 = 0, n1 = 0, n2 = 0, n3 = 0;
#pragma unroll
        for (int q = 0; q < 8; q += 2) {
            ulonglong2 ha = hp2[q];
            ulonglong2 hc = hp2[q + 1];
            r0 = ffma2(wr_[2 * q + 0], ha.x, r0);
            r1 = ffma2(wr_[2 * q + 1], ha.y, r1);
            r2 = ffma2(wr_[2 * q + 2], hc.x, r2);
            r3 = ffma2(wr_[2 * q + 3], hc.y, r3);
            z0 = ffma2(wz_[2 * q + 0], ha.x, z0);
            z1 = ffma2(wz_[2 * q + 1], ha.y, z1);
            z2 = ffma2(wz_[2 * q + 2], hc.x, z2);
            z3 = ffma2(wz_[2 * q + 3], hc.y, z3);
            n0 = ffma2(wn_[2 * q + 0], ha.x, n0);
            n1 = ffma2(wn_[2 * q + 1], ha.y, n1);
            n2 = ffma2(wn_[2 * q + 2], hc.x, n2);
            n3 = ffma2(wn_[2 * q + 3], hc.y, n3);
        }
        float lo, hi;
        upk2(fadd2(fadd2(r0, r1), fadd2(r2, r3)), lo, hi);
        float pr = lo + hi;
        upk2(fadd2(fadd2(z0, z1), fadd2(z2, z3)), lo, hi);
        float pz = lo + hi;
        upk2(fadd2(fadd2(n0, n1), fadd2(n2, n3)), lo, hi);
        float pn = lo + hi;
        pr += __shfl_xor_sync(0xffffffffu, pr, 1);
        pz += __shfl_xor_sync(0xffffffffu, pz, 1);
        pn += __shfl_xor_sync(0xffffffffu, pn, 1);
        if (p == 0) {
            float r = fast_sig(xr + pr + br);
            float z = fast_sig(xz + pz + bz);
            float n = fast_tanh(fmaf(r, pn + bn, xn));
            float hn = fmaf(z, hprev - n, n);
            hbuf[(s & 1) ^ 1][j] = hn;
            hprev = hn;
            if (s >= s_real0 && t < tot) psum += hn;
        }
        xr = xrn; xz = xzn; xn = xnn;
    }
    if (p == 0) atomicAdd(&pool[b * 2 * GRUD + dir * GRUD + j], psum);
}

// ---------------- head ----------------
__global__ void head_kernel(const float* __restrict__ pool,
                            const float* __restrict__ W_fus, const float* __restrict__ b_fus,
                            const float* __restrict__ W_c1, const float* __restrict__ b_c1,
                            const float* __restrict__ W_c2, const float* __restrict__ b_c2,
                            float* __restrict__ out) {
    int b = blockIdx.x;
    int t = threadIdx.x;
    __shared__ float sf[GRUD];
    __shared__ float sh1[128];
    __shared__ float sred[4];
    const float invN = 1.0f / (float)NSEQ;
    if (t < GRUD) {
        float s = b_fus[t];
        for (int d = 0; d < 2 * GRUD; d++)
            s = fmaf(W_fus[t * 2 * GRUD + d], pool[b * 2 * GRUD + d] * invN, s);
        sf[t] = s;
    }
    __syncthreads();
    {
        float s = b_c1[t];
        for (int g = 0; g < GRUD; g++) s = fmaf(W_c1[t * GRUD + g], sf[g], s);
        sh1[t] = fmaxf(s, 0.f);
    }
    __syncthreads();
    float v = W_c2[t] * sh1[t];
#pragma unroll
    for (int off = 16; off > 0; off >>= 1) v += __shfl_xor_sync(0xffffffffu, v, off);
    if ((t & 31) == 0) sred[t >> 5] = v;
    __syncthreads();
    if (t == 0) {
        float o = sred[0] + sred[1] + sred[2] + sred[3] + b_c2[0];
        out[b] = 1.f / (1.f + expf(-o));
    }
}

// ---------------- launch ----------------
extern "C" void kernel_launch(void* const* d_in, const int* in_sizes, int n_in,
                              void* d_out, int out_size) {
    const float* req    = (const float*)d_in[0];
    const float* code   = (const float*)d_in[1];
    const float* adj    = (const float*)d_in[2];
    const int*   total  = (const int*)  d_in[3];
    const float* W_proj = (const float*)d_in[4];
    const float* b_proj = (const float*)d_in[5];
    const float* W_g1   = (const float*)d_in[6];
    const float* b_g1   = (const float*)d_in[7];
    const float* a_g1   = (const float*)d_in[8];
    const float* W_g2   = (const float*)d_in[9];
    const float* b_g2   = (const float*)d_in[10];
    const float* a_g2   = (const float*)d_in[11];
    const float* Wih_f  = (const float*)d_in[12];
    const float* Whh_f  = (const float*)d_in[13];
    const float* bih_f  = (const float*)d_in[14];
    const float* bhh_f  = (const float*)d_in[15];
    const float* Wih_b  = (const float*)d_in[16];
    const float* Whh_b  = (const float*)d_in[17];
    const float* bih_b  = (const float*)d_in[18];
    const float* bhh_b  = (const float*)d_in[19];
    const float* W_fus  = (const float*)d_in[20];
    const float* b_fus  = (const float*)d_in[21];
    const float* W_c1   = (const float*)d_in[22];
    const float* b_c1   = (const float*)d_in[23];
    const float* W_c2   = (const float*)d_in[24];
    const float* b_c2   = (const float*)d_in[25];
    float* out = (float*)d_out;

    void *pabf, *pwbf, *ppbf, *pwg1, *pwg2, *ph1b, *pg1b, *ph2b, *pgatb;
    void *pwif, *pwib, *ps1s, *ps1d, *ps2s, *ps2d, *pxall, *ppool, *pel, *pdeg;
    cudaGetSymbolAddress(&pabf, g_abf);
    cudaGetSymbolAddress(&pwbf, g_wbf);
    cudaGetSymbolAddress(&ppbf, g_pbf);
    cudaGetSymbolAddress(&pwg1, g_wg1b);
    cudaGetSymbolAddress(&pwg2, g_wg2b);
    cudaGetSymbolAddress(&ph1b, g_h1b);
    cudaGetSymbolAddress(&pg1b, g_g1b);
    cudaGetSymbolAddress(&ph2b, g_h2b);
    cudaGetSymbolAddress(&pgatb, g_gatb);
    cudaGetSymbolAddress(&pwif, g_wifb);
    cudaGetSymbolAddress(&pwib, g_wibb);
    cudaGetSymbolAddress(&ps1s, g_s1s);
    cudaGetSymbolAddress(&ps1d, g_s1d);
    cudaGetSymbolAddress(&ps2s, g_s2s);
    cudaGetSymbolAddress(&ps2d, g_s2d);
    cudaGetSymbolAddress(&pxall, g_xall);
    cudaGetSymbolAddress(&ppool, g_pool);
    cudaGetSymbolAddress(&pel, g_el);
    cudaGetSymbolAddress(&pdeg, g_deg);

    unsigned short* fabf = (unsigned short*)pabf;
    unsigned short* fwbf = (unsigned short*)pwbf;
    unsigned short* fpbf = (unsigned short*)ppbf;
    unsigned short* fwg1 = (unsigned short*)pwg1;
    unsigned short* fwg2 = (unsigned short*)pwg2;
    unsigned short* fh1b = (unsigned short*)ph1b;
    unsigned short* fg1b = (unsigned short*)pg1b;
    unsigned short* fh2b = (unsigned short*)ph2b;
    unsigned short* fgatb = (unsigned short*)pgatb;
    unsigned short* fwif = (unsigned short*)pwif;
    unsigned short* fwib = (unsigned short*)pwib;
    float* fxall = (float*)pxall;
    unsigned short* fel = (unsigned short*)pel;
    int* fdeg = (int*)pdeg;

    // #1 CSR build (float4) + s-array + pool zeroing
    build_csr_kernel<<<MTOT / 8, 256>>>(adj, fel, fdeg, (float*)ps1s, (float*)ps1d,
                                        (float*)ps2s, (float*)ps2d, (float*)ppool);
    // #2 concat + bf16 input
    {
        size_t groups = (size_t)MTOT * (FEAT / 4);
        conv_a_kernel<<<(unsigned)((groups + 255) / 256), 256>>>(
            (const float4*)req, (const float4*)code, (ull*)pabf);
    }
    // #3 W_proj bf16
    conv_w_kernel<<<(HIDD * FEAT / 4 + 255) / 256, 256>>>(
        (const float4*)W_proj, (ull*)pwbf, HIDD * FEAT / 4);
    // #4 proj HMMA (PROFILED SLOT)
    hmma_smem_kernel<FEAT, HIDD, 0><<<MTOT / 64, 256>>>(
        fabf, fwbf, b_proj, nullptr, fpbf, nullptr, nullptr, nullptr, 0);
    // #5 W_g1 bf16
    conv_w_kernel<<<(HIDD * HIDD / 4 + 255) / 256, 256>>>(
        (const float4*)W_g1, (ull*)pwg1, HIDD * HIDD / 4);
    // #6 GAT1 GEMM HMMA + fused svec
    hmma_smem_kernel<HIDD, HIDD, 1><<<MTOT / 64, 256>>>(
        fpbf, fwg1, b_g1, a_g1, fh1b, (float*)ps1s, (float*)ps1d, nullptr, 0);
    // #7 GAT1 attention -> bf16
    gat_attb_kernel<HIDD, 1, 1><<<dim3(NSEQ / 8, BB), 256>>>(fh1b, fel, fdeg,
        (const float*)ps1s, (const float*)ps1d, total, nullptr, fg1b);
    // #8 W_g2 bf16
    conv_w_kernel<<<(GATD * HIDD / 4 + 255) / 256, 256>>>(
        (const float4*)W_g2, (ull*)pwg2, GATD * HIDD / 4);
    // #9 GAT2 GEMM HMMA + fused svec
    hmma_smem_kernel<HIDD, GATD, 1><<<MTOT / 64, 256>>>(
        fg1b, fwg2, b_g2, a_g2, fh2b, (float*)ps2s, (float*)ps2d, nullptr, 0);
    // #10 GAT2 attention -> bf16
    gat_attb_kernel<GATD, 0, 1><<<dim3(NSEQ / 8, BB), 256>>>(fh2b, fel, fdeg,
        (const float*)ps2s, (const float*)ps2d, total, nullptr, fgatb);
    // #11 Wih_f / Wih_b bf16
    conv_w_kernel<<<(192 * GATD / 4 + 255) / 256, 256>>>(
        (const float4*)Wih_f, (ull*)pwif, 192 * GATD / 4);
    conv_w_kernel<<<(192 * GATD / 4 + 255) / 256, 256>>>(
        (const float4*)Wih_b, (ull*)pwib, 192 * GATD / 4);
    // #12 GRU input projections via HMMA (fwd | bwd), fp32 out strided into xall
    hmma_smem_kernel<GATD, 192, 2><<<MTOT / 64, 256>>>(
        fgatb, fwif, bih_f, nullptr, nullptr, nullptr, nullptr, fxall, 384);
    hmma_smem_kernel<GATD, 192, 2><<<MTOT / 64, 256>>>(
        fgatb, fwib, bih_b, nullptr, nullptr, nullptr, nullptr, fxall + 192, 384);
    // #13 chunked-parallel GRU scan (GCH=64, GWU=128) + fused masked pool
    gru_kernel<<<dim3(BB, 2, NCHK), 128>>>((const float*)pxall, Whh_f, bhh_f, Whh_b, bhh_b,
                                           total, (float*)ppool);
    // #14 head
    head_kernel<<<BB, 128>>>((const float*)ppool, W_fus, b_fus, W_c1, b_c1, W_c2, b_c2, out);
}